// round 3
// baseline (speedup 1.0000x reference)
#include <cuda_runtime.h>
#include <cstdint>

// Grid constants (match reference float32 arithmetic)
#define N_PIX_HI   512
#define NV_HI      256
#define N_PIX_LO   128
#define NV_LO      64

#define C_PIX_HI      0.025f
#define C_FOV_HALF_HI 6.3875f      // 0.5*(512-1)*0.025
#define C_DV_HI       3.125f
#define C_VEL0_HI    -404.6875f    // -400 - 0.5*(12.5-3.125)

// Reciprocals of the float32 constants, computed in double at compile time so
// multiply matches the reference's division to <=1 ulp (no div.rn.f32 sequence:
// saves ~6M MUFU + ~30M FFMA over the whole launch).
__device__ __constant__ float INV_PIX_HI = (float)(1.0 / (double)C_PIX_HI);
__device__ __constant__ float INV_DV_HI  = (float)(1.0 / (double)C_DV_HI);

// Per-point splat of trilinear weights directly into the LO-RES cube.
// mean over the 4x4x4 oversample block == sum of hi-res contributions / 64.
// Corners i0,i0+1 sharing a lo-res block are merged (axis weights sum to 1),
// so expected atomics/point = (1.25)^3 ≈ 1.95 instead of 8.
__device__ __forceinline__ void splat_point(
    float rav, float decv, float velv, float fluxv,
    float inv_pix, float inv_dv, float* __restrict__ out)
{
    float x = (rav  + C_FOV_HALF_HI) * inv_pix;
    float y = (decv + C_FOV_HALF_HI) * inv_pix;
    float v = (velv - C_VEL0_HI)     * inv_dv;

    float xf = floorf(x), yf = floorf(y), vf = floorf(v);
    int ix0 = (int)xf, iy0 = (int)yf, iv0 = (int)vf;

    bool valid = (ix0 >= 0) & (ix0 < N_PIX_HI - 1) &
                 (iy0 >= 0) & (iy0 < N_PIX_HI - 1) &
                 (iv0 >= 0) & (iv0 < NV_HI - 1);
    if (!valid) return;

    float fx = x - xf, fy = y - yf, fv = v - vf;
    float f = fluxv * (1.0f / 64.0f);

    // Per-axis lo-res targets: split only when the hi-res corner pair
    // straddles a 4-wide block boundary (i0 % 4 == 3).
    int  bx0 = ix0 >> 2;
    bool sx  = (ix0 & 3) == 3;
    float wx0 = sx ? (1.0f - fx) : 1.0f;

    int  by0 = iy0 >> 2;
    bool sy  = (iy0 & 3) == 3;
    float wy0 = sy ? (1.0f - fy) : 1.0f;

    int  bv0 = iv0 >> 2;
    bool sv  = (iv0 & 3) == 3;
    float wv0 = sv ? (1.0f - fv) : 1.0f;

    int base00 = (bv0 * N_PIX_LO + by0) * N_PIX_LO;
    atomicAdd(out + base00 + bx0, f * wv0 * wy0 * wx0);
    if (sx) atomicAdd(out + base00 + bx0 + 1, f * wv0 * wy0 * fx);

    if (sy) {
        int base01 = base00 + N_PIX_LO;
        atomicAdd(out + base01 + bx0, f * wv0 * fy * wx0);
        if (sx) atomicAdd(out + base01 + bx0 + 1, f * wv0 * fy * fx);
    }
    if (sv) {
        int base10 = base00 + N_PIX_LO * N_PIX_LO;
        atomicAdd(out + base10 + bx0, f * fv * wy0 * wx0);
        if (sx) atomicAdd(out + base10 + bx0 + 1, f * fv * wy0 * fx);
        if (sy) {
            int base11 = base10 + N_PIX_LO;
            atomicAdd(out + base11 + bx0, f * fv * fy * wx0);
            if (sx) atomicAdd(out + base11 + bx0 + 1, f * fv * fy * fx);
        }
    }
}

__global__ void __launch_bounds__(256) splat_kernel(
    const float4* __restrict__ ra4,
    const float4* __restrict__ dec4,
    const float4* __restrict__ vel4,
    const float4* __restrict__ flux4,
    float* __restrict__ out,   // [NV_LO, N_PIX_LO, N_PIX_LO]
    int M4)                    // number of float4 groups
{
    int i = blockIdx.x * blockDim.x + threadIdx.x;
    if (i >= M4) return;

    float inv_pix = INV_PIX_HI;
    float inv_dv  = INV_DV_HI;

    // 4 fully-coalesced LDG.128 up front -> MLP_p1 = 4, latency hidden
    float4 r = ra4[i];
    float4 d = dec4[i];
    float4 v = vel4[i];
    float4 f = flux4[i];

    splat_point(r.x, d.x, v.x, f.x, inv_pix, inv_dv, out);
    splat_point(r.y, d.y, v.y, f.y, inv_pix, inv_dv, out);
    splat_point(r.z, d.z, v.z, f.z, inv_pix, inv_dv, out);
    splat_point(r.w, d.w, v.w, f.w, inv_pix, inv_dv, out);
}

// Tail kernel for M not divisible by 4 (M=2,000,000 is, but stay safe).
__global__ void splat_tail_kernel(
    const float* __restrict__ ra,
    const float* __restrict__ dec,
    const float* __restrict__ vel,
    const float* __restrict__ flux,
    float* __restrict__ out,
    int start, int M)
{
    int i = start + blockIdx.x * blockDim.x + threadIdx.x;
    if (i >= M) return;
    splat_point(ra[i], dec[i], vel[i], flux[i], INV_PIX_HI, INV_DV_HI, out);
}

extern "C" void kernel_launch(void* const* d_in, const int* in_sizes, int n_in,
                              void* d_out, int out_size)
{
    const float* ra   = (const float*)d_in[0];
    const float* dec  = (const float*)d_in[1];
    const float* vel  = (const float*)d_in[2];
    const float* flux = (const float*)d_in[3];
    float* out = (float*)d_out;
    int M = in_sizes[0];

    cudaMemsetAsync(out, 0, (size_t)out_size * sizeof(float));

    int M4 = M >> 2;
    if (M4 > 0) {
        int threads = 256;
        int blocks = (M4 + threads - 1) / threads;
        splat_kernel<<<blocks, threads>>>(
            (const float4*)ra, (const float4*)dec,
            (const float4*)vel, (const float4*)flux, out, M4);
    }
    int tail = M - (M4 << 2);
    if (tail > 0) {
        splat_tail_kernel<<<1, 256>>>(ra, dec, vel, flux, out, M4 << 2, M);
    }
}

// round 11
// speedup vs baseline: 1.0720x; 1.0720x over previous
#include <cuda_runtime.h>
#include <cstdint>

// Grid constants (match reference float32 arithmetic)
#define N_PIX_HI   512
#define NV_HI      256
#define N_PIX_LO   128
#define NV_LO      64

#define C_PIX_HI      0.025f
#define C_FOV_HALF_HI 6.3875f      // 0.5*(512-1)*0.025
#define C_DV_HI       3.125f
#define C_VEL0_HI    -404.6875f    // -400 - 0.5*(12.5-3.125)

// Reciprocals of the float32 constants, computed in double at compile time so
// multiply matches the reference's division to <=1 ulp.
__device__ __constant__ float INV_PIX_HI = (float)(1.0 / (double)C_PIX_HI);
__device__ __constant__ float INV_DV_HI  = (float)(1.0 / (double)C_DV_HI);

// Predicated global float reduction: issues @p RED.E.ADD.F32 with no branch,
// no BSSY/BSYNC. Predicated-off lanes generate no L1/L2 wavefront and never
// dereference the (possibly garbage) address.
__device__ __forceinline__ void pred_red(float* addr, float val, bool p)
{
    asm volatile(
        "{\n\t"
        ".reg .pred p0;\n\t"
        "setp.ne.u32 p0, %0, 0;\n\t"
        "@p0 red.global.add.f32 [%1], %2;\n\t"
        "}"
        :: "r"((int)p), "l"(addr), "f"(val) : "memory");
}

// Branch-free splat of one point's trilinear weights into the LO-RES cube.
// mean over the 4x4x4 oversample block == sum of hi-res contributions / 64.
// Hi-res corners i0,i0+1 sharing a lo-res block merge (axis weights sum to 1);
// a split only occurs when i0 % 4 == 3 (prob 0.25 per axis).
__device__ __forceinline__ void splat_point(
    float rav, float decv, float velv, float fluxv,
    float inv_pix, float inv_dv, float* __restrict__ out)
{
    // identical arithmetic to the passing R3 kernel
    float x = (rav  + C_FOV_HALF_HI) * inv_pix;
    float y = (decv + C_FOV_HALF_HI) * inv_pix;
    float v = (velv - C_VEL0_HI)     * inv_dv;

    float xf = floorf(x), yf = floorf(y), vf = floorf(v);
    int ix0 = (int)xf, iy0 = (int)yf, iv0 = (int)vf;
    float fx = x - xf, fy = y - yf, fv = v - vf;

    bool valid = ((unsigned)ix0 < (unsigned)(N_PIX_HI - 1)) &
                 ((unsigned)iy0 < (unsigned)(N_PIX_HI - 1)) &
                 ((unsigned)iv0 < (unsigned)(NV_HI - 1));

    float f = fluxv * (1.0f / 64.0f);

    bool sx = (ix0 & 3) == 3;
    bool sy = (iy0 & 3) == 3;
    bool sv = (iv0 & 3) == 3;

    float wx0 = sx ? (1.0f - fx) : 1.0f;   // FSEL, no branch
    float wy0 = sy ? (1.0f - fy) : 1.0f;
    float wv0 = sv ? (1.0f - fv) : 1.0f;

    int bx0 = ix0 >> 2;
    int by0 = iy0 >> 2;
    int bv0 = iv0 >> 2;

    // partial weight products
    float a0 = f * wv0;          // v-lo
    float a1 = f * fv;           // v-hi (only used when sv)
    float b00 = a0 * wy0;
    float b01 = a0 * fy;
    float b10 = a1 * wy0;
    float b11 = a1 * fy;

    // base address of corner (lo,lo,lo)
    float* p000 = out + ((bv0 * N_PIX_LO + by0) * N_PIX_LO + bx0);

    // predicates for the 8 (merged) corners
    bool px   = valid & sx;
    bool py   = valid & sy;
    bool pxy  = px & sy;
    bool pv   = valid & sv;
    bool pvx  = pv & sx;
    bool pvy  = pv & sy;
    bool pvxy = pvx & sy;

    const int SY = N_PIX_LO;                 // +y stride
    const int SV = N_PIX_LO * N_PIX_LO;      // +v stride

    pred_red(p000,               b00 * wx0, valid);
    pred_red(p000 + 1,           b00 * fx,  px);
    pred_red(p000 + SY,          b01 * wx0, py);
    pred_red(p000 + SY + 1,      b01 * fx,  pxy);
    pred_red(p000 + SV,          b10 * wx0, pv);
    pred_red(p000 + SV + 1,      b10 * fx,  pvx);
    pred_red(p000 + SV + SY,     b11 * wx0, pvy);
    pred_red(p000 + SV + SY + 1, b11 * fx,  pvxy);
}

__global__ void __launch_bounds__(256) splat_kernel(
    const float4* __restrict__ ra4,
    const float4* __restrict__ dec4,
    const float4* __restrict__ vel4,
    const float4* __restrict__ flux4,
    float* __restrict__ out,   // [NV_LO, N_PIX_LO, N_PIX_LO]
    int M4)
{
    int i = blockIdx.x * blockDim.x + threadIdx.x;
    if (i >= M4) return;

    float inv_pix = INV_PIX_HI;
    float inv_dv  = INV_DV_HI;

    // 4 fully-coalesced LDG.128 front-batched -> MLP_p1 = 4
    float4 r = ra4[i];
    float4 d = dec4[i];
    float4 v = vel4[i];
    float4 f = flux4[i];

    splat_point(r.x, d.x, v.x, f.x, inv_pix, inv_dv, out);
    splat_point(r.y, d.y, v.y, f.y, inv_pix, inv_dv, out);
    splat_point(r.z, d.z, v.z, f.z, inv_pix, inv_dv, out);
    splat_point(r.w, d.w, v.w, f.w, inv_pix, inv_dv, out);
}

// Tail kernel for M not divisible by 4 (M = 2,000,000 is; kept for safety —
// with tail == 0 at capture time this launch is skipped entirely).
__global__ void splat_tail_kernel(
    const float* __restrict__ ra,
    const float* __restrict__ dec,
    const float* __restrict__ vel,
    const float* __restrict__ flux,
    float* __restrict__ out,
    int start, int M)
{
    int i = start + blockIdx.x * blockDim.x + threadIdx.x;
    if (i >= M) return;
    splat_point(ra[i], dec[i], vel[i], flux[i], INV_PIX_HI, INV_DV_HI, out);
}

extern "C" void kernel_launch(void* const* d_in, const int* in_sizes, int n_in,
                              void* d_out, int out_size)
{
    const float* ra   = (const float*)d_in[0];
    const float* dec  = (const float*)d_in[1];
    const float* vel  = (const float*)d_in[2];
    const float* flux = (const float*)d_in[3];
    float* out = (float*)d_out;
    int M = in_sizes[0];

    cudaMemsetAsync(out, 0, (size_t)out_size * sizeof(float));

    int M4 = M >> 2;
    if (M4 > 0) {
        int threads = 256;
        int blocks = (M4 + threads - 1) / threads;
        splat_kernel<<<blocks, threads>>>(
            (const float4*)ra, (const float4*)dec,
            (const float4*)vel, (const float4*)flux, out, M4);
    }
    int tail = M - (M4 << 2);
    if (tail > 0) {
        splat_tail_kernel<<<1, 256>>>(ra, dec, vel, flux, out, M4 << 2, M);
    }
}